// round 10
// baseline (speedup 1.0000x reference)
#include <cuda_runtime.h>
#include <cuda_fp16.h>
#include <cuda_pipeline.h>
#include <math.h>

#define Bn   256
#define IC   1152
#define En   8
#define NC   10
#define DV   16
#define JD   160     // NC*DV

// hat kernel tiling
#define HK_ICHUNK 32
#define HK_NCHUNK (IC / HK_ICHUNK)   // 36
#define HK_BTILE  32
#define HK_NBT    (Bn / HK_BTILE)    // 8

// routing kernel: 384 threads = 48 octets; chunk = 48 i's, 24 chunks, 3 buffers
#define RT_THREADS 384
#define RT_WARPS   12
#define CH2        48
#define NCHUNKS2   (IC / CH2)        // 24
#define ROWU4      21                // uint4 per padded smem row (84 words)
#define U4B        (CH2 * ROWU4)     // 1008 uint4 per buffer
#define SMH_BYTES  (3 * U4B * 16)    // 48384 (triple buffered)

// Scratch (static device arrays; no cudaMalloc allowed)
__device__ __half g_hat[(size_t)Bn * IC * JD];            // 94.4 MB
__device__ __half g_Wt2[(size_t)IC * 5 * 32 * 8];         // lane-interleaved fp16 W
__device__ __half g_xh[(size_t)Bn * IC * En];             // x in fp16
__device__ float  g_c0[(size_t)IC * NC];                  // softmax(bias) per i
__device__ float  g_part0[(size_t)Bn * HK_NCHUNK * JD];   // pass-0 partials

// ---------------------------------------------------------------------------
// Kernel A: x -> fp16
// ---------------------------------------------------------------------------
__global__ __launch_bounds__(256) void xcvt_kernel(const float* __restrict__ x)
{
    const int idx = blockIdx.x * 256 + threadIdx.x;
    if (idx < Bn * IC * En / 4) {
        const float4 v = __ldg(reinterpret_cast<const float4*>(x) + idx);
        __half2* o = reinterpret_cast<__half2*>(g_xh) + 2 * idx;
        o[0] = __floats2half2_rn(v.x, v.y);
        o[1] = __floats2half2_rn(v.z, v.w);
    }
}

// ---------------------------------------------------------------------------
// Kernel B: Wt2 fp16 lane-interleaved layout (8 i's per block) + c0 softmax.
// ---------------------------------------------------------------------------
__global__ __launch_bounds__(256) void prep_W(
    const float* __restrict__ W, const float* __restrict__ bias)
{
    const int i0 = blockIdx.x * 8;
    __shared__ float sw[8][1280 + 80];
    for (int o = threadIdx.x; o < 8 * 1280; o += 256) {
        const int ii = o / 1280, k = o - ii * 1280;
        sw[ii][k + (k >> 4)] = __ldg(W + (size_t)(i0 + ii) * 1280 + k);
    }
    if (threadIdx.x < 128) {
        const int il = threadIdx.x >> 4, l = threadIdx.x & 15;
        float e = (l < NC) ? __expf(__ldg(&bias[(i0 + il) * NC + l])) : 0.f;
        float se = e;
#pragma unroll
        for (int off = 1; off < 16; off <<= 1)
            se += __shfl_xor_sync(0xffffffffu, se, off, 16);
        if (l < NC) g_c0[(i0 + il) * NC + l] = e * __fdividef(1.f, se);
    }
    __syncthreads();

    const int wi = threadIdx.x >> 5, lane = threadIdx.x & 31;
    const int i = i0 + wi;
#pragma unroll
    for (int c = 0; c < 5; c++) {
        __half h[8];
#pragma unroll
        for (int s = 0; s < 8; s++) {
            int jd, e;
            if (c < 4) { jd = 4 * lane + 2 * (c >> 1) + (s & 1); e = 4 * (c & 1) + (s >> 1); }
            else       { jd = 128 + lane; e = s; }
            const int j = jd >> 4, d = jd & 15;
            const int src = (j * 8 + e) * 16 + d;
            h[s] = __float2half_rn(sw[wi][src + (src >> 4)]);
        }
        *reinterpret_cast<uint4*>(g_Wt2 + (((size_t)i * 5 + c) * 32 + lane) * 8) =
            *reinterpret_cast<const uint4*>(h);
    }
}

// ---------------------------------------------------------------------------
// Kernel C: hat via HFMA2 (unchanged from R9 — measured good).
// ---------------------------------------------------------------------------
__global__ __launch_bounds__(256, 2) void hat_s0_kernel()
{
    const int chunk = blockIdx.x;
    const int bt    = blockIdx.y;
    const int tid   = threadIdx.x;
    const int w     = tid >> 5;
    const int lane  = tid & 31;
    const int i0    = chunk * HK_ICHUNK;
    const int b0    = bt * HK_BTILE + w * 4;

    float acc[4][5];
#pragma unroll
    for (int bb = 0; bb < 4; bb++)
#pragma unroll
        for (int k = 0; k < 5; k++) acc[bb][k] = 0.f;

    const __half2 z2 = __float2half2_rn(0.f);

    for (int il8 = 0; il8 < HK_ICHUNK / 8; il8++) {
        __half2 acc2[4][3];
#pragma unroll
        for (int bb = 0; bb < 4; bb++)
#pragma unroll
            for (int g = 0; g < 3; g++) acc2[bb][g] = z2;

        for (int il = 0; il < 8; il++) {
            const int i = i0 + il8 * 8 + il;

            uint4 wq[5];
            const uint4* wp = reinterpret_cast<const uint4*>(g_Wt2 + (size_t)i * 1280);
#pragma unroll
            for (int c = 0; c < 5; c++) wq[c] = __ldg(wp + c * 32 + lane);
            const __half2* W2 = reinterpret_cast<const __half2*>(wq);

            const __half2 c0A2 = __float2half2_rn(__ldg(&g_c0[i * NC + (lane >> 2)]));
            const __half2 c0C2 = __float2half2_rn(__ldg(&g_c0[i * NC + 8 + (lane >> 4)]));

#pragma unroll
            for (int bb = 0; bb < 4; bb++) {
                const int b = b0 + bb;
                const uint4 xq = __ldg(reinterpret_cast<const uint4*>(
                    g_xh + ((size_t)b * IC + i) * En));
                const __half2* x2 = reinterpret_cast<const __half2*>(&xq);
                const __half2 e0 = __low2half2(x2[0]), e1 = __high2half2(x2[0]);
                const __half2 e2 = __low2half2(x2[1]), e3 = __high2half2(x2[1]);
                const __half2 e4 = __low2half2(x2[2]), e5 = __high2half2(x2[2]);
                const __half2 e6 = __low2half2(x2[3]), e7 = __high2half2(x2[3]);

                __half2 sP[2];
#pragma unroll
                for (int p = 0; p < 2; p++) {
                    __half2 slo = __hmul2(e0, W2[8 * p]);
                    slo = __hfma2(e1, W2[8 * p + 1], slo);
                    slo = __hfma2(e2, W2[8 * p + 2], slo);
                    slo = __hfma2(e3, W2[8 * p + 3], slo);
                    __half2 shi = __hmul2(e4, W2[8 * p + 4]);
                    shi = __hfma2(e5, W2[8 * p + 5], shi);
                    shi = __hfma2(e6, W2[8 * p + 6], shi);
                    shi = __hfma2(e7, W2[8 * p + 7], shi);
                    sP[p] = __hadd2(slo, shi);
                }
                __half2 sC0 = __hmul2(x2[0], W2[16]);
                sC0 = __hfma2(x2[1], W2[17], sC0);
                __half2 sC1 = __hmul2(x2[2], W2[18]);
                sC1 = __hfma2(x2[3], W2[19], sC1);
                const __half2 sC = __hadd2(sC0, sC1);

                __half* hp = g_hat + ((size_t)b * IC + i) * JD;
                union { uint2 u; __half2 h[2]; } pk;
                pk.h[0] = sP[0]; pk.h[1] = sP[1];
                *reinterpret_cast<uint2*>(hp + 4 * lane) = pk.u;
                hp[128 + lane] = __hadd(__low2half(sC), __high2half(sC));

                acc2[bb][0] = __hfma2(c0A2, sP[0], acc2[bb][0]);
                acc2[bb][1] = __hfma2(c0A2, sP[1], acc2[bb][1]);
                acc2[bb][2] = __hfma2(c0C2, sC, acc2[bb][2]);
            }
        }

#pragma unroll
        for (int bb = 0; bb < 4; bb++) {
            const float2 fa = __half22float2(acc2[bb][0]);
            const float2 fb = __half22float2(acc2[bb][1]);
            const float2 fc = __half22float2(acc2[bb][2]);
            acc[bb][0] += fa.x; acc[bb][1] += fa.y;
            acc[bb][2] += fb.x; acc[bb][3] += fb.y;
            acc[bb][4] += fc.x + fc.y;
        }
    }

#pragma unroll
    for (int bb = 0; bb < 4; bb++) {
        float* pp = g_part0 + ((size_t)(b0 + bb) * HK_NCHUNK + chunk) * JD;
        *reinterpret_cast<float4*>(pp + 4 * lane) =
            make_float4(acc[bb][0], acc[bb][1], acc[bb][2], acc[bb][3]);
        pp[128 + lane] = acc[bb][4];
    }
}

// ---------------------------------------------------------------------------
// Kernel D: routing, fused A+B. Octet-per-i: thread h owns j=h (+ 8+h, h<2).
// Row stored interleaved: logical uint4 col c -> phys (c&1 ? 10+c/2 : c/2)
// so each thread's two LDS.128 hit 8 distinct bank-groups per phase.
// Triple buffer + single barrier per chunk (issue ch+1 vs compute ch-1
// differ by 2 mod 3 -> no overwrite race).
// ---------------------------------------------------------------------------
extern __shared__ uint4 smu4[];   // 3 buffers x 48 rows x 21 uint4

__device__ __forceinline__ void load_chunk(int b, int ch, int tid)
{
    const uint4* src =
        reinterpret_cast<const uint4*>(g_hat + ((size_t)b * IC + ch * CH2) * JD);
    uint4* dst = smu4 + (ch % 3) * U4B;
#pragma unroll
    for (int k = 0; k < 3; k++) {
        const int q = tid + k * RT_THREADS;
        if (k < 2 || q < CH2 * 20) {
            const int row = q / 20, col = q - row * 20;
            const int phys = (col & 1) ? 10 + (col >> 1) : (col >> 1);
            __pipeline_memcpy_async(dst + row * ROWU4 + phys, src + q, 16);
        }
    }
    __pipeline_commit();
}

__global__ __launch_bounds__(RT_THREADS, 2) void route_kernel(
    const float* __restrict__ bias, float* __restrict__ out)
{
    __shared__ float sred[RT_WARPS * JD];      // 7680 B
    __shared__ float s_sm[JD], u_f[JD], scale_sm[NC];
    __shared__ __align__(16) __half2 us2[JD / 2];

    const int b    = blockIdx.x;
    const int tid  = threadIdx.x;
    const int w    = tid >> 5;
    const int lane = tid & 31;
    const int h    = tid & 7;           // j-slot within octet
    const int oct  = (tid >> 3) & 0x3f; // octet within block = row within chunk
    const int octl = lane >> 3;         // octet within warp
    const bool two = (h < 2);
    (void)octl;

    load_chunk(b, 0, tid);              // prefetch chunk 0 behind v0 compute

    // ---- v0 = squash(sum of pass-0 partials) ----
    if (tid < JD) {
        float s = 0.f;
#pragma unroll
        for (int c = 0; c < HK_NCHUNK; c++)
            s += g_part0[((size_t)b * HK_NCHUNK + c) * JD + tid];
        s_sm[tid] = s;
    }
    __syncthreads();
    if (tid < NC) {
        float s2 = 0.f;
#pragma unroll
        for (int d = 0; d < DV; d++) { float v = s_sm[tid * DV + d]; s2 = fmaf(v, v, s2); }
        scale_sm[tid] = s2 / (1.0f + s2) * rsqrtf(s2);
    }
    __syncthreads();
    if (tid < JD) u_f[tid] = scale_sm[tid >> 4] * s_sm[tid];
    __syncthreads();
    if (tid < JD / 2) us2[tid] = __floats2half2_rn(u_f[2 * tid], u_f[2 * tid + 1]);
    __syncthreads();

    for (int pass = 0; pass < 2; pass++) {
        // u slices for this thread's j's -> registers
        __half2 u0[8], u1[8];
#pragma unroll
        for (int m = 0; m < 8; m++) u0[m] = us2[h * 8 + m];
#pragma unroll
        for (int m = 0; m < 8; m++) u1[m] = us2[(8 + h) * 8 + m];

        float acc0[16], acc1[16];
#pragma unroll
        for (int d = 0; d < 16; d++) { acc0[d] = 0.f; acc1[d] = 0.f; }

        for (int ch = 0; ch < NCHUNKS2; ch++) {
            if (ch + 1 < NCHUNKS2) {
                load_chunk(b, ch + 1, tid);
                __pipeline_wait_prior(1);
            } else {
                __pipeline_wait_prior(0);
            }
            __syncthreads();   // chunk ch visible; laggards past compute(ch-1)

            const uint4* row = smu4 + (ch % 3) * U4B + oct * ROWU4;
            const int i = ch * CH2 + oct;

            // rows (kept in registers for the weighted sum)
            const uint4 q0 = row[h];
            const uint4 q1 = row[10 + h];
            uint4 r0, r1;
            if (two) { r0 = row[8 + h]; r1 = row[18 + h]; }

            // agreement dot + exp
            const __half2* a0 = reinterpret_cast<const __half2*>(&q0);
            const __half2* a1 = reinterpret_cast<const __half2*>(&q1);
            __half2 d2 = __float2half2_rn(0.f);
#pragma unroll
            for (int m = 0; m < 4; m++) d2 = __hfma2(a0[m], u0[m], d2);
#pragma unroll
            for (int m = 0; m < 4; m++) d2 = __hfma2(a1[m], u0[4 + m], d2);
            const float e0 = __expf(__low2float(d2) + __high2float(d2) +
                                    __ldg(&bias[i * NC + h]));
            float e1 = 0.f;
            if (two) {
                const __half2* b0p = reinterpret_cast<const __half2*>(&r0);
                const __half2* b1p = reinterpret_cast<const __half2*>(&r1);
                __half2 f2 = __float2half2_rn(0.f);
#pragma unroll
                for (int m = 0; m < 4; m++) f2 = __hfma2(b0p[m], u1[m], f2);
#pragma unroll
                for (int m = 0; m < 4; m++) f2 = __hfma2(b1p[m], u1[4 + m], f2);
                e1 = __expf(__low2float(f2) + __high2float(f2) +
                            __ldg(&bias[i * NC + 8 + h]));
            }

            // octet softmax (lanes differing in bits 0..2 share an octet)
            float se = e0 + e1;
            se += __shfl_xor_sync(0xffffffffu, se, 1);
            se += __shfl_xor_sync(0xffffffffu, se, 2);
            se += __shfl_xor_sync(0xffffffffu, se, 4);
            const float inv = __fdividef(1.f, se);
            const float c0 = e0 * inv;
            const float c1 = e1 * inv;

            // fused weighted accumulate (rows already in registers)
#pragma unroll
            for (int m = 0; m < 4; m++) {
                const float2 fa = __half22float2(a0[m]);
                const float2 fb = __half22float2(a1[m]);
                acc0[2 * m]         = fmaf(c0, fa.x, acc0[2 * m]);
                acc0[2 * m + 1]     = fmaf(c0, fa.y, acc0[2 * m + 1]);
                acc0[8 + 2 * m]     = fmaf(c0, fb.x, acc0[8 + 2 * m]);
                acc0[8 + 2 * m + 1] = fmaf(c0, fb.y, acc0[8 + 2 * m + 1]);
            }
            if (two) {
                const __half2* b0p = reinterpret_cast<const __half2*>(&r0);
                const __half2* b1p = reinterpret_cast<const __half2*>(&r1);
#pragma unroll
                for (int m = 0; m < 4; m++) {
                    const float2 fa = __half22float2(b0p[m]);
                    const float2 fb = __half22float2(b1p[m]);
                    acc1[2 * m]         = fmaf(c1, fa.x, acc1[2 * m]);
                    acc1[2 * m + 1]     = fmaf(c1, fa.y, acc1[2 * m + 1]);
                    acc1[8 + 2 * m]     = fmaf(c1, fb.x, acc1[8 + 2 * m]);
                    acc1[8 + 2 * m + 1] = fmaf(c1, fb.y, acc1[8 + 2 * m + 1]);
                }
            }
        }

        if (pass == 0) load_chunk(b, 0, tid);   // prefetch pass-1 chunk 0

        // ---- fold 4 octets within warp (xor 8,16 keep h fixed) ----
#pragma unroll
        for (int d = 0; d < 16; d++) {
            acc0[d] += __shfl_xor_sync(0xffffffffu, acc0[d], 8);
            acc0[d] += __shfl_xor_sync(0xffffffffu, acc0[d], 16);
            acc1[d] += __shfl_xor_sync(0xffffffffu, acc1[d], 8);
            acc1[d] += __shfl_xor_sync(0xffffffffu, acc1[d], 16);
        }
        if (lane < 8) {
            float4* sp = reinterpret_cast<float4*>(&sred[w * JD + h * DV]);
#pragma unroll
            for (int m = 0; m < 4; m++)
                sp[m] = make_float4(acc0[4 * m], acc0[4 * m + 1],
                                    acc0[4 * m + 2], acc0[4 * m + 3]);
            if (two) {
                float4* sq = reinterpret_cast<float4*>(&sred[w * JD + (8 + h) * DV]);
#pragma unroll
                for (int m = 0; m < 4; m++)
                    sq[m] = make_float4(acc1[4 * m], acc1[4 * m + 1],
                                        acc1[4 * m + 2], acc1[4 * m + 3]);
            }
        }
        __syncthreads();

        // ---- cross-warp reduce + squash ----
        if (tid < JD) {
            float s = 0.f;
#pragma unroll
            for (int w2 = 0; w2 < RT_WARPS; w2++) s += sred[w2 * JD + tid];
            s_sm[tid] = s;
        }
        __syncthreads();
        if (tid < NC) {
            float s2 = 0.f;
#pragma unroll
            for (int d = 0; d < DV; d++) { float v = s_sm[tid * DV + d]; s2 = fmaf(v, v, s2); }
            scale_sm[tid] = s2 / (1.0f + s2) * rsqrtf(s2);
        }
        __syncthreads();
        if (tid < JD) {
            const float v = scale_sm[tid >> 4] * s_sm[tid];
            if (pass == 0) u_f[tid] += v;                 // u = v0 + v1 (telescoped)
            else           out[(size_t)b * JD + tid] = v; // final v2
        }
        __syncthreads();
        if (pass == 0 && tid < JD / 2)
            us2[tid] = __floats2half2_rn(u_f[2 * tid], u_f[2 * tid + 1]);
        __syncthreads();
    }
}

// ---------------------------------------------------------------------------
extern "C" void kernel_launch(void* const* d_in, const int* in_sizes, int n_in,
                              void* d_out, int out_size)
{
    const float* x    = (const float*)d_in[0];
    const float* W    = (const float*)d_in[1];
    const float* bias = (const float*)d_in[2];
    float* out        = (float*)d_out;

    cudaFuncSetAttribute(route_kernel,
                         cudaFuncAttributeMaxDynamicSharedMemorySize, SMH_BYTES);

    xcvt_kernel<<<(Bn * IC * En / 4 + 255) / 256, 256>>>(x);
    prep_W<<<IC / 8, 256>>>(W, bias);
    hat_s0_kernel<<<dim3(HK_NCHUNK, HK_NBT), 256>>>();
    route_kernel<<<Bn, RT_THREADS, SMH_BYTES>>>(bias, out);
}

// round 11
// speedup vs baseline: 1.0228x; 1.0228x over previous
#include <cuda_runtime.h>
#include <cuda_fp16.h>
#include <cuda_pipeline.h>
#include <math.h>

#define Bn   256
#define IC   1152
#define En   8
#define NC   10
#define DV   16
#define JD   160     // NC*DV

// hat kernel tiling (smaller chunks -> more blocks -> 3/SM)
#define HK_ICHUNK 16
#define HK_NCHUNK (IC / HK_ICHUNK)   // 72
#define HK_BTILE  32
#define HK_NBT    (Bn / HK_BTILE)    // 8

// routing kernel (R9 structure — measured best)
#define RT_THREADS 384
#define RT_WARPS   12
#define CH         96
#define NCHUNKS    (IC / CH)         // 12
#define ROWU4      21                // uint4 per padded smem row
#define U4_PER_BUF (CH * ROWU4)
#define SMH_BYTES  (2 * U4_PER_BUF * 16)

// Scratch (static device arrays; no cudaMalloc allowed)
__device__ __half g_hat[(size_t)Bn * IC * JD];            // 94.4 MB
__device__ __half g_Wt2[(size_t)IC * 5 * 32 * 8];         // lane-interleaved fp16 W
__device__ __half g_xh[(size_t)Bn * IC * En];             // x in fp16
__device__ float  g_c0[(size_t)IC * NC];                  // softmax(bias) per i
__device__ float  g_part0[(size_t)Bn * HK_NCHUNK * JD];   // pass-0 partials

// ---------------------------------------------------------------------------
// Kernel A: x -> fp16
// ---------------------------------------------------------------------------
__global__ __launch_bounds__(256) void xcvt_kernel(const float* __restrict__ x)
{
    const int idx = blockIdx.x * 256 + threadIdx.x;
    if (idx < Bn * IC * En / 4) {
        const float4 v = __ldg(reinterpret_cast<const float4*>(x) + idx);
        __half2* o = reinterpret_cast<__half2*>(g_xh) + 2 * idx;
        o[0] = __floats2half2_rn(v.x, v.y);
        o[1] = __floats2half2_rn(v.z, v.w);
    }
}

// ---------------------------------------------------------------------------
// Kernel B: Wt2 fp16 lane-interleaved layout (8 i's per block) + c0 softmax.
// ---------------------------------------------------------------------------
__global__ __launch_bounds__(256) void prep_W(
    const float* __restrict__ W, const float* __restrict__ bias)
{
    const int i0 = blockIdx.x * 8;
    __shared__ float sw[8][1280 + 80];
    for (int o = threadIdx.x; o < 8 * 1280; o += 256) {
        const int ii = o / 1280, k = o - ii * 1280;
        sw[ii][k + (k >> 4)] = __ldg(W + (size_t)(i0 + ii) * 1280 + k);
    }
    if (threadIdx.x < 128) {
        const int il = threadIdx.x >> 4, l = threadIdx.x & 15;
        float e = (l < NC) ? __expf(__ldg(&bias[(i0 + il) * NC + l])) : 0.f;
        float se = e;
#pragma unroll
        for (int off = 1; off < 16; off <<= 1)
            se += __shfl_xor_sync(0xffffffffu, se, off, 16);
        if (l < NC) g_c0[(i0 + il) * NC + l] = e * __fdividef(1.f, se);
    }
    __syncthreads();

    const int wi = threadIdx.x >> 5, lane = threadIdx.x & 31;
    const int i = i0 + wi;
#pragma unroll
    for (int c = 0; c < 5; c++) {
        __half h[8];
#pragma unroll
        for (int s = 0; s < 8; s++) {
            int jd, e;
            if (c < 4) { jd = 4 * lane + 2 * (c >> 1) + (s & 1); e = 4 * (c & 1) + (s >> 1); }
            else       { jd = 128 + lane; e = s; }
            const int j = jd >> 4, d = jd & 15;
            const int src = (j * 8 + e) * 16 + d;
            h[s] = __float2half_rn(sw[wi][src + (src >> 4)]);
        }
        *reinterpret_cast<uint4*>(g_Wt2 + (((size_t)i * 5 + c) * 32 + lane) * 8) =
            *reinterpret_cast<const uint4*>(h);
    }
}

// ---------------------------------------------------------------------------
// Kernel C: hat via HFMA2, lane owns jd {4l..4l+3, 128+l}. 3 blocks/SM.
// ---------------------------------------------------------------------------
__global__ __launch_bounds__(256, 3) void hat_s0_kernel()
{
    const int chunk = blockIdx.x;          // 0..71
    const int bt    = blockIdx.y;          // 0..7
    const int tid   = threadIdx.x;
    const int w     = tid >> 5;
    const int lane  = tid & 31;
    const int i0    = chunk * HK_ICHUNK;
    const int b0    = bt * HK_BTILE + w * 4;

    float acc[4][5];
#pragma unroll
    for (int bb = 0; bb < 4; bb++)
#pragma unroll
        for (int k = 0; k < 5; k++) acc[bb][k] = 0.f;

    const __half2 z2 = __float2half2_rn(0.f);

    for (int il8 = 0; il8 < HK_ICHUNK / 8; il8++) {
        __half2 acc2[4][3];
#pragma unroll
        for (int bb = 0; bb < 4; bb++)
#pragma unroll
            for (int g = 0; g < 3; g++) acc2[bb][g] = z2;

        for (int il = 0; il < 8; il++) {
            const int i = i0 + il8 * 8 + il;

            uint4 wq[5];
            const uint4* wp = reinterpret_cast<const uint4*>(g_Wt2 + (size_t)i * 1280);
#pragma unroll
            for (int c = 0; c < 5; c++) wq[c] = __ldg(wp + c * 32 + lane);
            const __half2* W2 = reinterpret_cast<const __half2*>(wq);

            const __half2 c0A2 = __float2half2_rn(__ldg(&g_c0[i * NC + (lane >> 2)]));
            const __half2 c0C2 = __float2half2_rn(__ldg(&g_c0[i * NC + 8 + (lane >> 4)]));

#pragma unroll
            for (int bb = 0; bb < 4; bb++) {
                const int b = b0 + bb;
                const uint4 xq = __ldg(reinterpret_cast<const uint4*>(
                    g_xh + ((size_t)b * IC + i) * En));
                const __half2* x2 = reinterpret_cast<const __half2*>(&xq);
                const __half2 e0 = __low2half2(x2[0]), e1 = __high2half2(x2[0]);
                const __half2 e2 = __low2half2(x2[1]), e3 = __high2half2(x2[1]);
                const __half2 e4 = __low2half2(x2[2]), e5 = __high2half2(x2[2]);
                const __half2 e6 = __low2half2(x2[3]), e7 = __high2half2(x2[3]);

                __half2 sP[2];
#pragma unroll
                for (int p = 0; p < 2; p++) {
                    __half2 slo = __hmul2(e0, W2[8 * p]);
                    slo = __hfma2(e1, W2[8 * p + 1], slo);
                    slo = __hfma2(e2, W2[8 * p + 2], slo);
                    slo = __hfma2(e3, W2[8 * p + 3], slo);
                    __half2 shi = __hmul2(e4, W2[8 * p + 4]);
                    shi = __hfma2(e5, W2[8 * p + 5], shi);
                    shi = __hfma2(e6, W2[8 * p + 6], shi);
                    shi = __hfma2(e7, W2[8 * p + 7], shi);
                    sP[p] = __hadd2(slo, shi);
                }
                __half2 sC0 = __hmul2(x2[0], W2[16]);
                sC0 = __hfma2(x2[1], W2[17], sC0);
                __half2 sC1 = __hmul2(x2[2], W2[18]);
                sC1 = __hfma2(x2[3], W2[19], sC1);
                const __half2 sC = __hadd2(sC0, sC1);

                __half* hp = g_hat + ((size_t)b * IC + i) * JD;
                union { uint2 u; __half2 h[2]; } pk;
                pk.h[0] = sP[0]; pk.h[1] = sP[1];
                *reinterpret_cast<uint2*>(hp + 4 * lane) = pk.u;
                hp[128 + lane] = __hadd(__low2half(sC), __high2half(sC));

                acc2[bb][0] = __hfma2(c0A2, sP[0], acc2[bb][0]);
                acc2[bb][1] = __hfma2(c0A2, sP[1], acc2[bb][1]);
                acc2[bb][2] = __hfma2(c0C2, sC, acc2[bb][2]);
            }
        }

#pragma unroll
        for (int bb = 0; bb < 4; bb++) {
            const float2 fa = __half22float2(acc2[bb][0]);
            const float2 fb = __half22float2(acc2[bb][1]);
            const float2 fc = __half22float2(acc2[bb][2]);
            acc[bb][0] += fa.x; acc[bb][1] += fa.y;
            acc[bb][2] += fb.x; acc[bb][3] += fb.y;
            acc[bb][4] += fc.x + fc.y;
        }
    }

#pragma unroll
    for (int bb = 0; bb < 4; bb++) {
        float* pp = g_part0 + ((size_t)(b0 + bb) * HK_NCHUNK + chunk) * JD;
        *reinterpret_cast<float4*>(pp + 4 * lane) =
            make_float4(acc[bb][0], acc[bb][1], acc[bb][2], acc[bb][3]);
        pp[128 + lane] = acc[bb][4];
    }
}

// ---------------------------------------------------------------------------
// Kernel D: routing — exact R9 structure (measured best: 53.2us).
// ---------------------------------------------------------------------------
extern __shared__ uint4 smu4[];

__device__ __forceinline__ void load_chunk(int b, int ch, int buf, int tid)
{
    const uint4* src =
        reinterpret_cast<const uint4*>(g_hat + ((size_t)b * IC + ch * CH) * JD);
    uint4* dst = smu4 + buf * U4_PER_BUF;
#pragma unroll
    for (int k = 0; k < 5; k++) {
        const int q = tid + k * RT_THREADS;
        const int row = q / 20, col = q % 20;
        __pipeline_memcpy_async(dst + row * ROWU4 + col, src + q, 16);
    }
    __pipeline_commit();
}

__global__ __launch_bounds__(RT_THREADS, 2) void route_kernel(
    const float* __restrict__ bias, float* __restrict__ out)
{
    __shared__ float c_f[CH * NC];
    __shared__ float sred[RT_WARPS * JD];
    __shared__ float s_sm[JD], u_f[JD], scale_sm[NC];
    __shared__ __align__(16) __half2 us2[JD / 2];

    const int b    = blockIdx.x;
    const int tid  = threadIdx.x;
    const int w    = tid >> 5;
    const int lane = tid & 31;
    const int quad = tid >> 2;
    const int g    = tid & 3;
    const int jn   = (g < 2) ? 3 : 2;
    const int rB   = lane & 7;
    const int gB   = lane >> 3;

    load_chunk(b, 0, 0, tid);

    if (tid < JD) {
        float s = 0.f;
        for (int c = 0; c < HK_NCHUNK; c++)
            s += g_part0[((size_t)b * HK_NCHUNK + c) * JD + tid];
        s_sm[tid] = s;
    }
    __syncthreads();
    if (tid < NC) {
        float s2 = 0.f;
#pragma unroll
        for (int d = 0; d < DV; d++) { float v = s_sm[tid * DV + d]; s2 = fmaf(v, v, s2); }
        scale_sm[tid] = s2 / (1.0f + s2) * rsqrtf(s2);
    }
    __syncthreads();
    if (tid < JD) u_f[tid] = scale_sm[tid >> 4] * s_sm[tid];
    __syncthreads();
    if (tid < JD / 2) us2[tid] = __floats2half2_rn(u_f[2 * tid], u_f[2 * tid + 1]);
    __syncthreads();

    for (int pass = 0; pass < 2; pass++) {
        float acc[5][8];
#pragma unroll
        for (int m = 0; m < 5; m++)
#pragma unroll
            for (int d = 0; d < 8; d++) acc[m][d] = 0.f;

        for (int ch = 0; ch < NCHUNKS; ch++) {
            const int buf = ch & 1;
            if (ch + 1 < NCHUNKS) {
                load_chunk(b, ch + 1, (ch + 1) & 1, tid);
                __pipeline_wait_prior(1);
            } else {
                __pipeline_wait_prior(0);
            }
            __syncthreads();

            // Phase A: quad-per-i agreement + softmax
            {
                const uint4* row = smu4 + buf * U4_PER_BUF + quad * ROWU4;
                const int ig = ch * CH + quad;
                float av[3];
                float se = 0.f;
#pragma unroll
                for (int jj = 0; jj < 3; jj++) {
                    if (jj < jn) {
                        const int j = g + 4 * jj;
                        const uint4 q0 = row[2 * j];
                        const uint4 q1 = row[2 * j + 1];
                        const __half2* ha = reinterpret_cast<const __half2*>(&q0);
                        const __half2* hb = reinterpret_cast<const __half2*>(&q1);
                        __half2 a2 = __float2half2_rn(0.f);
#pragma unroll
                        for (int m = 0; m < 4; m++) a2 = __hfma2(ha[m], us2[j * 8 + m], a2);
#pragma unroll
                        for (int m = 0; m < 4; m++) a2 = __hfma2(hb[m], us2[j * 8 + 4 + m], a2);
                        av[jj] = __expf(__low2float(a2) + __high2float(a2) +
                                        __ldg(&bias[ig * NC + j]));
                        se += av[jj];
                    }
                }
                se += __shfl_xor_sync(0xffffffffu, se, 1);
                se += __shfl_xor_sync(0xffffffffu, se, 2);
                const float inv = __fdividef(1.f, se);
#pragma unroll
                for (int jj = 0; jj < 3; jj++)
                    if (jj < jn) c_f[quad * NC + g + 4 * jj] = av[jj] * inv;
            }
            __syncthreads();

            // Phase B: vectorized weighted sum (uint4 per lane)
            {
                const int row = w * 8 + rB;
                const uint4* rowp = smu4 + buf * U4_PER_BUF + row * ROWU4;
                const float* crow = c_f + row * NC;
#pragma unroll
                for (int m = 0; m < 5; m++) {
                    const int col = gB + 4 * m;
                    const uint4 q = rowp[col];
                    const float c = crow[col >> 1];
                    const __half2* h2 = reinterpret_cast<const __half2*>(&q);
#pragma unroll
                    for (int n = 0; n < 4; n++) {
                        const float2 f = __half22float2(h2[n]);
                        acc[m][2 * n]     = fmaf(c, f.x, acc[m][2 * n]);
                        acc[m][2 * n + 1] = fmaf(c, f.y, acc[m][2 * n + 1]);
                    }
                }
            }
            __syncthreads();
        }

        if (pass == 0) load_chunk(b, 0, 0, tid);

#pragma unroll
        for (int m = 0; m < 5; m++)
#pragma unroll
            for (int d = 0; d < 8; d++) {
#pragma unroll
                for (int off = 1; off < 8; off <<= 1)
                    acc[m][d] += __shfl_xor_sync(0xffffffffu, acc[m][d], off);
            }
        if (rB == 0) {
#pragma unroll
            for (int m = 0; m < 5; m++) {
                const int jd0 = 8 * (gB + 4 * m);
                *reinterpret_cast<float4*>(&sred[w * JD + jd0]) =
                    make_float4(acc[m][0], acc[m][1], acc[m][2], acc[m][3]);
                *reinterpret_cast<float4*>(&sred[w * JD + jd0 + 4]) =
                    make_float4(acc[m][4], acc[m][5], acc[m][6], acc[m][7]);
            }
        }
        __syncthreads();

        if (tid < JD) {
            float s = 0.f;
#pragma unroll
            for (int w2 = 0; w2 < RT_WARPS; w2++) s += sred[w2 * JD + tid];
            s_sm[tid] = s;
        }
        __syncthreads();
        if (tid < NC) {
            float s2 = 0.f;
#pragma unroll
            for (int d = 0; d < DV; d++) { float v = s_sm[tid * DV + d]; s2 = fmaf(v, v, s2); }
            scale_sm[tid] = s2 / (1.0f + s2) * rsqrtf(s2);
        }
        __syncthreads();
        if (tid < JD) {
            const float v = scale_sm[tid >> 4] * s_sm[tid];
            if (pass == 0) u_f[tid] += v;
            else           out[(size_t)b * JD + tid] = v;
        }
        __syncthreads();
        if (pass == 0 && tid < JD / 2)
            us2[tid] = __floats2half2_rn(u_f[2 * tid], u_f[2 * tid + 1]);
        __syncthreads();
    }
}

// ---------------------------------------------------------------------------
extern "C" void kernel_launch(void* const* d_in, const int* in_sizes, int n_in,
                              void* d_out, int out_size)
{
    const float* x    = (const float*)d_in[0];
    const float* W    = (const float*)d_in[1];
    const float* bias = (const float*)d_in[2];
    float* out        = (float*)d_out;

    cudaFuncSetAttribute(route_kernel,
                         cudaFuncAttributeMaxDynamicSharedMemorySize, SMH_BYTES);

    xcvt_kernel<<<(Bn * IC * En / 4 + 255) / 256, 256>>>(x);
    prep_W<<<IC / 8, 256>>>(W, bias);
    hat_s0_kernel<<<dim3(HK_NCHUNK, HK_NBT), 256>>>();
    route_kernel<<<Bn, RT_THREADS, SMH_BYTES>>>(bias, out);
}

// round 12
// speedup vs baseline: 1.1950x; 1.1684x over previous
#include <cuda_runtime.h>
#include <cuda_fp16.h>
#include <cuda_pipeline.h>
#include <math.h>

#define Bn   256
#define IC   1152
#define En   8
#define NC   10
#define DV   16
#define JD   160     // NC*DV

// hat kernel tiling (R9 exact)
#define HK_ICHUNK 32
#define HK_NCHUNK (IC / HK_ICHUNK)   // 36
#define HK_BTILE  32
#define HK_NBT    (Bn / HK_BTILE)    // 8

// routing kernel: R9 structure, triple-buffered
#define RT_THREADS 384
#define RT_WARPS   12
#define CH         96
#define NCHUNKS    (IC / CH)         // 12
#define ROWU4      21                // uint4 per padded smem row
#define U4_PER_BUF (CH * ROWU4)      // 2016
#define SMH_BYTES  (3 * U4_PER_BUF * 16)   // 96768 (triple buffered)

// Scratch (static device arrays; no cudaMalloc allowed)
__device__ __half g_hat[(size_t)Bn * IC * JD];            // 94.4 MB
__device__ __half g_Wt2[(size_t)IC * 5 * 32 * 8];         // lane-interleaved fp16 W
__device__ __half g_xh[(size_t)Bn * IC * En];             // x in fp16
__device__ float  g_c0[(size_t)IC * NC];                  // softmax(bias) per i
__device__ float  g_part0[(size_t)Bn * HK_NCHUNK * JD];   // pass-0 partials

// ---------------------------------------------------------------------------
// Kernel A: x -> fp16
// ---------------------------------------------------------------------------
__global__ __launch_bounds__(256) void xcvt_kernel(const float* __restrict__ x)
{
    const int idx = blockIdx.x * 256 + threadIdx.x;
    if (idx < Bn * IC * En / 4) {
        const float4 v = __ldg(reinterpret_cast<const float4*>(x) + idx);
        __half2* o = reinterpret_cast<__half2*>(g_xh) + 2 * idx;
        o[0] = __floats2half2_rn(v.x, v.y);
        o[1] = __floats2half2_rn(v.z, v.w);
    }
}

// ---------------------------------------------------------------------------
// Kernel B: Wt2 fp16 lane-interleaved layout (8 i's per block) + c0 softmax.
// ---------------------------------------------------------------------------
__global__ __launch_bounds__(256) void prep_W(
    const float* __restrict__ W, const float* __restrict__ bias)
{
    const int i0 = blockIdx.x * 8;
    __shared__ float sw[8][1280 + 80];
    for (int o = threadIdx.x; o < 8 * 1280; o += 256) {
        const int ii = o / 1280, k = o - ii * 1280;
        sw[ii][k + (k >> 4)] = __ldg(W + (size_t)(i0 + ii) * 1280 + k);
    }
    if (threadIdx.x < 128) {
        const int il = threadIdx.x >> 4, l = threadIdx.x & 15;
        float e = (l < NC) ? __expf(__ldg(&bias[(i0 + il) * NC + l])) : 0.f;
        float se = e;
#pragma unroll
        for (int off = 1; off < 16; off <<= 1)
            se += __shfl_xor_sync(0xffffffffu, se, off, 16);
        if (l < NC) g_c0[(i0 + il) * NC + l] = e * __fdividef(1.f, se);
    }
    __syncthreads();

    const int wi = threadIdx.x >> 5, lane = threadIdx.x & 31;
    const int i = i0 + wi;
#pragma unroll
    for (int c = 0; c < 5; c++) {
        __half h[8];
#pragma unroll
        for (int s = 0; s < 8; s++) {
            int jd, e;
            if (c < 4) { jd = 4 * lane + 2 * (c >> 1) + (s & 1); e = 4 * (c & 1) + (s >> 1); }
            else       { jd = 128 + lane; e = s; }
            const int j = jd >> 4, d = jd & 15;
            const int src = (j * 8 + e) * 16 + d;
            h[s] = __float2half_rn(sw[wi][src + (src >> 4)]);
        }
        *reinterpret_cast<uint4*>(g_Wt2 + (((size_t)i * 5 + c) * 32 + lane) * 8) =
            *reinterpret_cast<const uint4*>(h);
    }
}

// ---------------------------------------------------------------------------
// Kernel C: hat via HFMA2 — R9 exact (measured best).
// ---------------------------------------------------------------------------
__global__ __launch_bounds__(256, 2) void hat_s0_kernel()
{
    const int chunk = blockIdx.x;
    const int bt    = blockIdx.y;
    const int tid   = threadIdx.x;
    const int w     = tid >> 5;
    const int lane  = tid & 31;
    const int i0    = chunk * HK_ICHUNK;
    const int b0    = bt * HK_BTILE + w * 4;

    float acc[4][5];
#pragma unroll
    for (int bb = 0; bb < 4; bb++)
#pragma unroll
        for (int k = 0; k < 5; k++) acc[bb][k] = 0.f;

    const __half2 z2 = __float2half2_rn(0.f);

    for (int il8 = 0; il8 < HK_ICHUNK / 8; il8++) {
        __half2 acc2[4][3];
#pragma unroll
        for (int bb = 0; bb < 4; bb++)
#pragma unroll
            for (int g = 0; g < 3; g++) acc2[bb][g] = z2;

        for (int il = 0; il < 8; il++) {
            const int i = i0 + il8 * 8 + il;

            uint4 wq[5];
            const uint4* wp = reinterpret_cast<const uint4*>(g_Wt2 + (size_t)i * 1280);
#pragma unroll
            for (int c = 0; c < 5; c++) wq[c] = __ldg(wp + c * 32 + lane);
            const __half2* W2 = reinterpret_cast<const __half2*>(wq);

            const __half2 c0A2 = __float2half2_rn(__ldg(&g_c0[i * NC + (lane >> 2)]));
            const __half2 c0C2 = __float2half2_rn(__ldg(&g_c0[i * NC + 8 + (lane >> 4)]));

#pragma unroll
            for (int bb = 0; bb < 4; bb++) {
                const int b = b0 + bb;
                const uint4 xq = __ldg(reinterpret_cast<const uint4*>(
                    g_xh + ((size_t)b * IC + i) * En));
                const __half2* x2 = reinterpret_cast<const __half2*>(&xq);
                const __half2 e0 = __low2half2(x2[0]), e1 = __high2half2(x2[0]);
                const __half2 e2 = __low2half2(x2[1]), e3 = __high2half2(x2[1]);
                const __half2 e4 = __low2half2(x2[2]), e5 = __high2half2(x2[2]);
                const __half2 e6 = __low2half2(x2[3]), e7 = __high2half2(x2[3]);

                __half2 sP[2];
#pragma unroll
                for (int p = 0; p < 2; p++) {
                    __half2 slo = __hmul2(e0, W2[8 * p]);
                    slo = __hfma2(e1, W2[8 * p + 1], slo);
                    slo = __hfma2(e2, W2[8 * p + 2], slo);
                    slo = __hfma2(e3, W2[8 * p + 3], slo);
                    __half2 shi = __hmul2(e4, W2[8 * p + 4]);
                    shi = __hfma2(e5, W2[8 * p + 5], shi);
                    shi = __hfma2(e6, W2[8 * p + 6], shi);
                    shi = __hfma2(e7, W2[8 * p + 7], shi);
                    sP[p] = __hadd2(slo, shi);
                }
                __half2 sC0 = __hmul2(x2[0], W2[16]);
                sC0 = __hfma2(x2[1], W2[17], sC0);
                __half2 sC1 = __hmul2(x2[2], W2[18]);
                sC1 = __hfma2(x2[3], W2[19], sC1);
                const __half2 sC = __hadd2(sC0, sC1);

                __half* hp = g_hat + ((size_t)b * IC + i) * JD;
                union { uint2 u; __half2 h[2]; } pk;
                pk.h[0] = sP[0]; pk.h[1] = sP[1];
                *reinterpret_cast<uint2*>(hp + 4 * lane) = pk.u;
                hp[128 + lane] = __hadd(__low2half(sC), __high2half(sC));

                acc2[bb][0] = __hfma2(c0A2, sP[0], acc2[bb][0]);
                acc2[bb][1] = __hfma2(c0A2, sP[1], acc2[bb][1]);
                acc2[bb][2] = __hfma2(c0C2, sC, acc2[bb][2]);
            }
        }

#pragma unroll
        for (int bb = 0; bb < 4; bb++) {
            const float2 fa = __half22float2(acc2[bb][0]);
            const float2 fb = __half22float2(acc2[bb][1]);
            const float2 fc = __half22float2(acc2[bb][2]);
            acc[bb][0] += fa.x; acc[bb][1] += fa.y;
            acc[bb][2] += fb.x; acc[bb][3] += fb.y;
            acc[bb][4] += fc.x + fc.y;
        }
    }

#pragma unroll
    for (int bb = 0; bb < 4; bb++) {
        float* pp = g_part0 + ((size_t)(b0 + bb) * HK_NCHUNK + chunk) * JD;
        *reinterpret_cast<float4*>(pp + 4 * lane) =
            make_float4(acc[bb][0], acc[bb][1], acc[bb][2], acc[bb][3]);
        pp[128 + lane] = acc[bb][4];
    }
}

// ---------------------------------------------------------------------------
// Kernel D: routing. R9 phases; triple buffer removes the post-Phase-B
// barrier (load(ch+2) -> buf (ch+2)%3, issued post-A-barrier; laggards in
// B(ch) read buf ch%3 — disjoint mod 3).
// ---------------------------------------------------------------------------
extern __shared__ uint4 smu4[];   // 3 buffers x CH x 21 uint4

__device__ __forceinline__ void load_chunk(int b, int ch, int tid)
{
    const uint4* src =
        reinterpret_cast<const uint4*>(g_hat + ((size_t)b * IC + ch * CH) * JD);
    uint4* dst = smu4 + (ch % 3) * U4_PER_BUF;
#pragma unroll
    for (int k = 0; k < 5; k++) {
        const int q = tid + k * RT_THREADS;
        const int row = q / 20, col = q % 20;
        __pipeline_memcpy_async(dst + row * ROWU4 + col, src + q, 16);
    }
    __pipeline_commit();
}

__global__ __launch_bounds__(RT_THREADS, 2) void route_kernel(
    const float* __restrict__ bias, float* __restrict__ out)
{
    __shared__ float c_f[CH * NC];
    __shared__ float sred[RT_WARPS * JD];
    __shared__ float s_sm[JD], u_f[JD], scale_sm[NC];
    __shared__ __align__(16) __half2 us2[JD / 2];

    const int b    = blockIdx.x;
    const int tid  = threadIdx.x;
    const int w    = tid >> 5;
    const int lane = tid & 31;
    const int quad = tid >> 2;
    const int g    = tid & 3;
    const int jn   = (g < 2) ? 3 : 2;
    const int rB   = lane & 7;
    const int gB   = lane >> 3;

    load_chunk(b, 0, tid);     // prefetch chunks 0,1 behind v0 compute
    load_chunk(b, 1, tid);

    if (tid < JD) {
        float s = 0.f;
#pragma unroll
        for (int c = 0; c < HK_NCHUNK; c++)
            s += g_part0[((size_t)b * HK_NCHUNK + c) * JD + tid];
        s_sm[tid] = s;
    }
    __syncthreads();
    if (tid < NC) {
        float s2 = 0.f;
#pragma unroll
        for (int d = 0; d < DV; d++) { float v = s_sm[tid * DV + d]; s2 = fmaf(v, v, s2); }
        scale_sm[tid] = s2 / (1.0f + s2) * rsqrtf(s2);
    }
    __syncthreads();
    if (tid < JD) u_f[tid] = scale_sm[tid >> 4] * s_sm[tid];
    __syncthreads();
    if (tid < JD / 2) us2[tid] = __floats2half2_rn(u_f[2 * tid], u_f[2 * tid + 1]);
    __syncthreads();

    for (int pass = 0; pass < 2; pass++) {
        float acc[5][8];
#pragma unroll
        for (int m = 0; m < 5; m++)
#pragma unroll
            for (int d = 0; d < 8; d++) acc[m][d] = 0.f;

        for (int ch = 0; ch < NCHUNKS; ch++) {
            if (ch + 1 < NCHUNKS) __pipeline_wait_prior(1);
            else                  __pipeline_wait_prior(0);
            __syncthreads();     // chunk ch visible to all threads

            // Phase A: quad-per-i agreement + softmax
            {
                const uint4* row = smu4 + (ch % 3) * U4_PER_BUF + quad * ROWU4;
                const int ig = ch * CH + quad;
                float av[3];
                float se = 0.f;
#pragma unroll
                for (int jj = 0; jj < 3; jj++) {
                    if (jj < jn) {
                        const int j = g + 4 * jj;
                        const uint4 q0 = row[2 * j];
                        const uint4 q1 = row[2 * j + 1];
                        const __half2* ha = reinterpret_cast<const __half2*>(&q0);
                        const __half2* hb = reinterpret_cast<const __half2*>(&q1);
                        __half2 a2 = __float2half2_rn(0.f);
#pragma unroll
                        for (int m = 0; m < 4; m++) a2 = __hfma2(ha[m], us2[j * 8 + m], a2);
#pragma unroll
                        for (int m = 0; m < 4; m++) a2 = __hfma2(hb[m], us2[j * 8 + 4 + m], a2);
                        av[jj] = __expf(__low2float(a2) + __high2float(a2) +
                                        __ldg(&bias[ig * NC + j]));
                        se += av[jj];
                    }
                }
                se += __shfl_xor_sync(0xffffffffu, se, 1);
                se += __shfl_xor_sync(0xffffffffu, se, 2);
                const float inv = __fdividef(1.f, se);
#pragma unroll
                for (int jj = 0; jj < 3; jj++)
                    if (jj < jn) c_f[quad * NC + g + 4 * jj] = av[jj] * inv;
            }
            __syncthreads();     // c_f ready; all threads past buf reads? no—
                                 // A read buf ch%3; B below reads it again (ok)

            if (ch + 2 < NCHUNKS) load_chunk(b, ch + 2, tid);  // buf (ch+2)%3

            // Phase B: vectorized weighted sum (uint4 per lane)
            {
                const int row = w * 8 + rB;
                const uint4* rowp = smu4 + (ch % 3) * U4_PER_BUF + row * ROWU4;
                const float* crow = c_f + row * NC;
#pragma unroll
                for (int m = 0; m < 5; m++) {
                    const int col = gB + 4 * m;
                    const uint4 q = rowp[col];
                    const float c = crow[col >> 1];
                    const __half2* h2 = reinterpret_cast<const __half2*>(&q);
#pragma unroll
                    for (int n = 0; n < 4; n++) {
                        const float2 f = __half22float2(h2[n]);
                        acc[m][2 * n]     = fmaf(c, f.x, acc[m][2 * n]);
                        acc[m][2 * n + 1] = fmaf(c, f.y, acc[m][2 * n + 1]);
                    }
                }
            }
            // no barrier: next iter's load targets buf (ch+3)%3 != ch%3,
            // and c_f is rewritten only after the next A-barrier.
            __syncwarp();
        }

        // fold rows within warp
#pragma unroll
        for (int m = 0; m < 5; m++)
#pragma unroll
            for (int d = 0; d < 8; d++) {
#pragma unroll
                for (int off = 1; off < 8; off <<= 1)
                    acc[m][d] += __shfl_xor_sync(0xffffffffu, acc[m][d], off);
            }
        if (rB == 0) {
#pragma unroll
            for (int m = 0; m < 5; m++) {
                const int jd0 = 8 * (gB + 4 * m);
                *reinterpret_cast<float4*>(&sred[w * JD + jd0]) =
                    make_float4(acc[m][0], acc[m][1], acc[m][2], acc[m][3]);
                *reinterpret_cast<float4*>(&sred[w * JD + jd0 + 4]) =
                    make_float4(acc[m][4], acc[m][5], acc[m][6], acc[m][7]);
            }
        }
        __syncthreads();

        if (pass == 0) {         // prefetch pass-1 chunks 0,1 (bufs 0,1 free:
            load_chunk(b, 0, tid);   // all threads past B(11) which used buf 2)
            load_chunk(b, 1, tid);
        }

        if (tid < JD) {
            float s = 0.f;
#pragma unroll
            for (int w2 = 0; w2 < RT_WARPS; w2++) s += sred[w2 * JD + tid];
            s_sm[tid] = s;
        }
        __syncthreads();
        if (tid < NC) {
            float s2 = 0.f;
#pragma unroll
            for (int d = 0; d < DV; d++) { float v = s_sm[tid * DV + d]; s2 = fmaf(v, v, s2); }
            scale_sm[tid] = s2 / (1.0f + s2) * rsqrtf(s2);
        }
        __syncthreads();
        if (tid < JD) {
            const float v = scale_sm[tid >> 4] * s_sm[tid];
            if (pass == 0) u_f[tid] += v;
            else           out[(size_t)b * JD + tid] = v;
        }
        __syncthreads();
        if (pass == 0 && tid < JD / 2)
            us2[tid] = __floats2half2_rn(u_f[2 * tid], u_f[2 * tid + 1]);
        __syncthreads();
    }
}

// ---------------------------------------------------------------------------
extern "C" void kernel_launch(void* const* d_in, const int* in_sizes, int n_in,
                              void* d_out, int out_size)
{
    const float* x    = (const float*)d_in[0];
    const float* W    = (const float*)d_in[1];
    const float* bias = (const float*)d_in[2];
    float* out        = (float*)d_out;

    cudaFuncSetAttribute(route_kernel,
                         cudaFuncAttributeMaxDynamicSharedMemorySize, SMH_BYTES);

    xcvt_kernel<<<(Bn * IC * En / 4 + 255) / 256, 256>>>(x);
    prep_W<<<IC / 8, 256>>>(W, bias);
    hat_s0_kernel<<<dim3(HK_NCHUNK, HK_NBT), 256>>>();
    route_kernel<<<Bn, RT_THREADS, SMH_BYTES>>>(bias, out);
}